// round 1
// baseline (speedup 1.0000x reference)
#include <cuda_runtime.h>
#include <math.h>
#include <stdint.h>

// ---------------- problem constants ----------------
#define BATCH   128
#define OBS_H   2
#define NTOK    291            // 2*(144+1)+1
#define M_TOK   (BATCH*NTOK)   // 37248 = 291 * 128  (exact 128-tiles)
#define D_EMB   384
#define NHEAD   6
#define HDIM    64
#define NLAYER  12
#define N_IMG   144
#define PK      192            // 8*8*3 patch features
#define M_PATCH (BATCH*OBS_H*N_IMG)   // 36864 = 288*128

// ---------------- scratch (device globals; no allocation allowed) ----------
__device__ float g_x  [M_TOK * D_EMB];     // residual stream
__device__ float g_y  [M_TOK * D_EMB];     // LN output / patch buffer (im2col fits: 7.1M < 14.3M)
__device__ float g_big[M_TOK * 1536];      // qkv (42.9M) / fc1 (57.2M)
__device__ float g_att[M_TOK * D_EMB];     // attention out / img tokens (14.2M fits)
__device__ float g_st [BATCH * OBS_H * D_EMB];

// ---------------- helpers ----------------
__device__ __forceinline__ float gelu_tanh(float v) {
    const float c = 0.7978845608028654f;
    float u = c * (v + 0.044715f * v * v * v);
    return 0.5f * v * (1.0f + tanhf(u));
}

// ---------------- SGEMM: C[M,N] = A[M,K] @ W[K,N] (+bias, +gelu, +residual) --
// BM=BN=128, BK=16, 256 threads, 8x8 microtile. M,N multiples of 128, K of 16.
template <int EPI>   // 0: +bias   1: +bias then gelu   2: +bias + R (residual)
__global__ void __launch_bounds__(256) sgemm(
    const float* __restrict__ A, const float* __restrict__ W,
    const float* __restrict__ bias, const float* __restrict__ R,
    float* __restrict__ C, int N, int K)
{
    __shared__ float As[16][128];
    __shared__ float Bs[16][128];
    const int tid = threadIdx.x;
    const int bm = blockIdx.y, bn = blockIdx.x;
    const float* Ab = A + (size_t)bm * 128 * K;
    const float* Wb = W + bn * 128;

    float acc[8][8];
#pragma unroll
    for (int i = 0; i < 8; i++)
#pragma unroll
        for (int j = 0; j < 8; j++) acc[i][j] = 0.f;

    const int tm = (tid >> 4) << 3;
    const int tn = (tid & 15) << 3;

    for (int kt = 0; kt < K; kt += 16) {
#pragma unroll
        for (int i = 0; i < 2; i++) {
            int idx = tid + 256 * i;
            int r = idx >> 2, c4 = (idx & 3) << 2;
            float4 av = *(const float4*)(Ab + (size_t)r * K + kt + c4);
            As[c4 + 0][r] = av.x; As[c4 + 1][r] = av.y;
            As[c4 + 2][r] = av.z; As[c4 + 3][r] = av.w;
            int rb = idx >> 5, cb = (idx & 31) << 2;
            *(float4*)(&Bs[rb][cb]) = *(const float4*)(Wb + (size_t)(kt + rb) * N + cb);
        }
        __syncthreads();
#pragma unroll
        for (int kk = 0; kk < 16; kk++) {
            float ra[8], rbv[8];
#pragma unroll
            for (int i = 0; i < 8; i++) ra[i] = As[kk][tm + i];
#pragma unroll
            for (int j = 0; j < 8; j++) rbv[j] = Bs[kk][tn + j];
#pragma unroll
            for (int i = 0; i < 8; i++)
#pragma unroll
                for (int j = 0; j < 8; j++) acc[i][j] = fmaf(ra[i], rbv[j], acc[i][j]);
        }
        __syncthreads();
    }

#pragma unroll
    for (int i = 0; i < 8; i++) {
        size_t row = (size_t)(bm * 128 + tm + i);
        size_t off = row * N + bn * 128 + tn;
#pragma unroll
        for (int j = 0; j < 8; j += 4) {
            float4 v;
            float* pv = &v.x;
#pragma unroll
            for (int q = 0; q < 4; q++) {
                float val = acc[i][j + q] + bias[bn * 128 + tn + j + q];
                if (EPI == 1) val = gelu_tanh(val);
                if (EPI == 2) val += R[off + j + q];
                pv[q] = val;
            }
            *(float4*)(C + off + j) = v;
        }
    }
}

// ---------------- LayerNorm (one 128-thread block per 384-wide row) --------
__device__ __forceinline__ void ln_row(const float* __restrict__ xr,
                                       const float* __restrict__ w,
                                       const float* __restrict__ b,
                                       float* __restrict__ yr)
{
    int tid = threadIdx.x;
    float v0 = xr[tid], v1 = xr[tid + 128], v2 = xr[tid + 256];
    float s = v0 + v1 + v2;
    float sq = v0 * v0 + v1 * v1 + v2 * v2;
#pragma unroll
    for (int o = 16; o; o >>= 1) {
        s  += __shfl_xor_sync(~0u, s,  o);
        sq += __shfl_xor_sync(~0u, sq, o);
    }
    __shared__ float ws[4], wq[4], red[2];
    int warp = tid >> 5, lane = tid & 31;
    if (!lane) { ws[warp] = s; wq[warp] = sq; }
    __syncthreads();
    if (tid == 0) {
        float S = ws[0] + ws[1] + ws[2] + ws[3];
        float Q = wq[0] + wq[1] + wq[2] + wq[3];
        float mean = S * (1.0f / 384.0f);
        red[0] = mean;
        red[1] = rsqrtf(Q * (1.0f / 384.0f) - mean * mean + 1e-5f);
    }
    __syncthreads();
    float mean = red[0], inv = red[1];
    yr[tid]       = (v0 - mean) * inv * w[tid]       + b[tid];
    yr[tid + 128] = (v1 - mean) * inv * w[tid + 128] + b[tid + 128];
    yr[tid + 256] = (v2 - mean) * inv * w[tid + 256] + b[tid + 256];
}

__global__ void ln_kernel(const float* __restrict__ x, const float* __restrict__ w,
                          const float* __restrict__ b, float* __restrict__ y)
{
    size_t row = blockIdx.x;
    ln_row(x + row * D_EMB, w, b, y + row * D_EMB);
}

__global__ void lnf_kernel(const float* __restrict__ x, const float* __restrict__ w,
                           const float* __restrict__ b, float* __restrict__ out)
{
    size_t bi = blockIdx.x;                          // 128 blocks: readout rows only
    ln_row(x + (bi * NTOK + (NTOK - 1)) * D_EMB, w, b, out + bi * D_EMB);
}

// ---------------- Attention: one block per (b, h); K,V resident in smem ----
// smem: K[291][65] + V[291][65] + P[8][292] + Q[8][64]  = 162,712 bytes
#define ATT_SMEM_FLOATS (291*65*2 + 8*292 + 8*64)
#define ATT_SMEM_BYTES  (ATT_SMEM_FLOATS * 4)

__global__ void __launch_bounds__(256) attn_kernel(const float* __restrict__ qkv,
                                                   float* __restrict__ out)
{
    extern __shared__ float sm[];
    float* Ks = sm;
    float* Vs = sm + 291 * 65;
    float* Ps = sm + 291 * 65 * 2;   // [8][292]
    float* Qs = Ps + 8 * 292;        // [8][64]

    int bh = blockIdx.x;
    int b = bh / NHEAD, h = bh % NHEAD;
    int tid = threadIdx.x, warp = tid >> 5, lane = tid & 31;
    const size_t base = (size_t)b * NTOK * 1152 + h * 64;

    for (int idx = tid; idx < NTOK * 64; idx += 256) {
        int j = idx >> 6, d = idx & 63;
        Ks[j * 65 + d] = qkv[base + (size_t)j * 1152 + 384 + d];
        Vs[j * 65 + d] = qkv[base + (size_t)j * 1152 + 768 + d];
    }
    __syncthreads();

    const float scale = rsqrtf(64.0f + 1e-8f);

    for (int t = warp; t < NTOK; t += 8) {
        __syncwarp();
        float* outr = out + ((size_t)b * NTOK + t) * D_EMB + h * 64;
        if (t == NTOK - 1) {
            // readout row: mask = -inf everywhere except self -> softmax is one-hot
            outr[lane]      = Vs[(NTOK - 1) * 65 + lane];
            outr[lane + 32] = Vs[(NTOK - 1) * 65 + lane + 32];
            continue;
        }
        const float* qr = qkv + base + (size_t)t * 1152;
        Qs[warp * 64 + lane]      = qr[lane];
        Qs[warp * 64 + lane + 32] = qr[lane + 32];
        __syncwarp();

        float s[10];
#pragma unroll
        for (int jc = 0; jc < 10; jc++) {
            int j = jc * 32 + lane;
            if (j < NTOK) {
                const float* kr = Ks + j * 65;
                const float* qs = Qs + warp * 64;
                float acc = 0.f;
#pragma unroll
                for (int d = 0; d < 64; d++) acc = fmaf(qs[d], kr[d], acc);
                s[jc] = acc * scale;
            } else s[jc] = -1e30f;
        }
        float m = s[0];
#pragma unroll
        for (int jc = 1; jc < 10; jc++) m = fmaxf(m, s[jc]);
#pragma unroll
        for (int o = 16; o; o >>= 1) m = fmaxf(m, __shfl_xor_sync(~0u, m, o));
        float sum = 0.f;
#pragma unroll
        for (int jc = 0; jc < 10; jc++) { s[jc] = expf(s[jc] - m); sum += s[jc]; }
#pragma unroll
        for (int o = 16; o; o >>= 1) sum += __shfl_xor_sync(~0u, sum, o);
        float inv = 1.0f / sum;
#pragma unroll
        for (int jc = 0; jc < 10; jc++) {
            int j = jc * 32 + lane;
            if (j < NTOK) Ps[warp * 292 + j] = s[jc];
        }
        __syncwarp();

        float o0 = 0.f, o1 = 0.f;
        const float* pp = Ps + warp * 292;
        for (int j = 0; j < NTOK; j++) {
            float pv = pp[j];
            o0 = fmaf(pv, Vs[j * 65 + lane],      o0);
            o1 = fmaf(pv, Vs[j * 65 + lane + 32], o1);
        }
        outr[lane]      = o0 * inv;
        outr[lane + 32] = o1 * inv;
    }
}

// ---------------- tokenizers ----------------
__global__ void st_kernel(const float* __restrict__ as, const float* __restrict__ w1,
                          const float* __restrict__ b1, const float* __restrict__ w2,
                          const float* __restrict__ b2, float* __restrict__ st)
{
    __shared__ float h1[32];
    int bt = blockIdx.x;          // 256
    int tid = threadIdx.x;        // 384
    float s0 = as[bt * 2], s1 = as[bt * 2 + 1];
    if (tid < 32) {
        float v = b1[tid] + s0 * w1[tid] + s1 * w1[32 + tid];
        h1[tid] = v > 0.f ? v : 0.f;
    }
    __syncthreads();
    float acc = b2[tid];
#pragma unroll
    for (int k = 0; k < 32; k++) acc = fmaf(h1[k], w2[k * 384 + tid], acc);
    st[(size_t)bt * 384 + tid] = acc;
}

__global__ void im2col_kernel(const float* __restrict__ img, float* __restrict__ patch)
{
    int idx = blockIdx.x * 256 + threadIdx.x;   // M_PATCH * 192
    int f = idx % 192;
    int rem = idx / 192;
    int pidx = rem % 144;
    int bt = rem / 144;
    int pr = f / 24, pc = (f % 24) / 3, c = f % 3;
    int hp = pidx / 12, wp = pidx % 12;
    patch[idx] = img[(((size_t)bt * 3 + c) * 96 + hp * 8 + pr) * 96 + wp * 8 + pc];
}

__global__ void assemble_kernel(const float* __restrict__ imgtok, const float* __restrict__ st,
                                const float* __restrict__ readout, const float* __restrict__ pos,
                                const float* __restrict__ img_temb, const float* __restrict__ st_temb,
                                float* __restrict__ x)
{
    int idx = blockIdx.x * 256 + threadIdx.x;   // M_TOK * 384
    int d = idx % 384;
    int rem = idx / 384;
    int tok = rem % NTOK;
    int b = rem / NTOK;
    float v;
    if (tok == NTOK - 1) {
        v = readout[d];
    } else {
        int t = tok / 145, r = tok % 145;
        if (r == 0) v = st[((size_t)(b * 2 + t)) * 384 + d] + st_temb[t * 384 + d];
        else        v = imgtok[((size_t)(b * 2 + t) * 144 + (r - 1)) * 384 + d] + img_temb[t * 384 + d];
    }
    x[idx] = v + pos[tok * 384 + d];
}

// ---------------- launch ----------------
extern "C" void kernel_launch(void* const* d_in, const int* in_sizes, int n_in,
                              void* d_out, int out_size)
{
    const float* images      = (const float*)d_in[0];
    const float* agent_state = (const float*)d_in[1];
    const float* img_proj_w  = (const float*)d_in[2];
    const float* img_proj_b  = (const float*)d_in[3];
    const float* img_temb    = (const float*)d_in[4];
    const float* st_w1       = (const float*)d_in[5];
    const float* st_b1       = (const float*)d_in[6];
    const float* st_w2       = (const float*)d_in[7];
    const float* st_b2       = (const float*)d_in[8];
    const float* st_temb     = (const float*)d_in[9];
    const float* readout     = (const float*)d_in[10];
    const float* pos         = (const float*)d_in[11];
    const float* ln1_w       = (const float*)d_in[12];
    const float* ln1_b       = (const float*)d_in[13];
    const float* attn_w      = (const float*)d_in[14];
    const float* attn_b      = (const float*)d_in[15];
    const float* proj_w      = (const float*)d_in[16];
    const float* proj_b      = (const float*)d_in[17];
    const float* ln2_w       = (const float*)d_in[18];
    const float* ln2_b       = (const float*)d_in[19];
    const float* fc_w        = (const float*)d_in[20];
    const float* fc_b        = (const float*)d_in[21];
    const float* fc2_w       = (const float*)d_in[22];
    const float* fc2_b       = (const float*)d_in[23];
    const float* lnf_w       = (const float*)d_in[24];
    const float* lnf_b       = (const float*)d_in[25];
    float* out = (float*)d_out;

    float *x, *y, *big, *att, *st;
    cudaGetSymbolAddress((void**)&x,   g_x);
    cudaGetSymbolAddress((void**)&y,   g_y);
    cudaGetSymbolAddress((void**)&big, g_big);
    cudaGetSymbolAddress((void**)&att, g_att);
    cudaGetSymbolAddress((void**)&st,  g_st);

    cudaFuncSetAttribute(attn_kernel, cudaFuncAttributeMaxDynamicSharedMemorySize, ATT_SMEM_BYTES);

    // ---- tokenizers ----
    st_kernel<<<BATCH * OBS_H, 384>>>(agent_state, st_w1, st_b1, st_w2, st_b2, st);
    im2col_kernel<<<(M_PATCH * PK) / 256, 256>>>(images, y);
    sgemm<0><<<dim3(3, M_PATCH / 128), 256>>>(y, img_proj_w, img_proj_b, nullptr, att, 384, PK);
    assemble_kernel<<<(M_TOK * D_EMB) / 256, 256>>>(att, st, readout, pos, img_temb, st_temb, x);

    // ---- transformer layers ----
    for (int l = 0; l < NLAYER; l++) {
        ln_kernel<<<M_TOK, 128>>>(x, ln1_w + l * 384, ln1_b + l * 384, y);
        sgemm<0><<<dim3(9, NTOK), 256>>>(y, attn_w + (size_t)l * 384 * 1152,
                                         attn_b + l * 1152, nullptr, big, 1152, 384);
        attn_kernel<<<BATCH * NHEAD, 256, ATT_SMEM_BYTES>>>(big, att);
        sgemm<2><<<dim3(3, NTOK), 256>>>(att, proj_w + (size_t)l * 384 * 384,
                                         proj_b + l * 384, x, x, 384, 384);
        ln_kernel<<<M_TOK, 128>>>(x, ln2_w + l * 384, ln2_b + l * 384, y);
        sgemm<1><<<dim3(12, NTOK), 256>>>(y, fc_w + (size_t)l * 384 * 1536,
                                          fc_b + l * 1536, nullptr, big, 1536, 384);
        sgemm<2><<<dim3(3, NTOK), 256>>>(big, fc2_w + (size_t)l * 1536 * 384,
                                         fc2_b + l * 384, x, x, 384, 1536);
    }

    // ---- final LN on readout rows ----
    lnf_kernel<<<BATCH, 128>>>(x, lnf_w, lnf_b, out);
}